// round 14
// baseline (speedup 1.0000x reference)
#include <cuda_runtime.h>
#include <math.h>
#include <cstdint>

#define DPROJ 8192
#define CIN   512
#define HW    196
#define NB    32
#define BC    128
#define KCH   98
#define NPAIR 10

typedef unsigned long long u64;

// Scratch (no cudaMalloc allowed)
__device__ int   g_h1[CIN], g_h2[CIN];
__device__ float g_s1[CIN], g_s2[CIN];
__device__ float g_Y[NB * DPROJ];

__constant__ int c_I[NPAIR] = {0,0,0,0,1,1,1,2,2,3};
__constant__ int c_J[NPAIR] = {0,1,2,3,1,2,3,2,3,3};

// ---------------------------------------------------------------------------
// f32x2 helpers (sm_103a packed fp32 pipe; IEEE fp32 per lane)
__device__ __forceinline__ u64 pack2(float x) {
    u64 r; asm("mov.b64 %0, {%1, %1};" : "=l"(r) : "f"(x)); return r;
}
__device__ __forceinline__ void fma2(u64& acc, u64 a, u64 b) {
    asm("fma.rn.f32x2 %0, %1, %2, %0;" : "+l"(acc) : "l"(a), "l"(b));
}
__device__ __forceinline__ float2 unpack2(u64 v) {
    float2 r; asm("mov.b64 {%0, %1}, %2;" : "=f"(r.x), "=f"(r.y) : "l"(v)); return r;
}

// ---------------------------------------------------------------------------
// Fused prep: float4 extract of (h,s) from S1/S2 rows + zero g_Y.
__global__ void prep_kernel(const float* __restrict__ S1,
                            const float* __restrict__ S2) {
    int blk = blockIdx.x;
    if (blk < 2 * CIN) {
        int which = blk >= CIN;
        int row = which ? blk - CIN : blk;
        const float4* p = reinterpret_cast<const float4*>((which ? S2 : S1) + (size_t)row * DPROJ);
        int*   h = which ? g_h2 : g_h1;
        float* s = which ? g_s2 : g_s1;
        for (int c4 = threadIdx.x; c4 < DPROJ / 4; c4 += 256) {
            float4 v = p[c4];
            if (v.x != 0.f) { h[row] = 4 * c4 + 0; s[row] = v.x; }
            if (v.y != 0.f) { h[row] = 4 * c4 + 1; s[row] = v.y; }
            if (v.z != 0.f) { h[row] = 4 * c4 + 2; s[row] = v.z; }
            if (v.w != 0.f) { h[row] = 4 * c4 + 3; s[row] = v.w; }
        }
    } else {
        int i = (blk - 2 * CIN) * 256 + threadIdx.x;
        reinterpret_cast<float4*>(g_Y)[i] = make_float4(0.f, 0.f, 0.f, 0.f);
    }
}

// ---------------------------------------------------------------------------
// Transposed, XOR-swizzled, SIGN-FOLDED tile load: dst logical [k][c].
// phys float index = k*BC + 4*((c>>2) ^ ((k>>1)&31)) + (c&3)
// Each channel row c is multiplied by sgn[c] (+-1) while staging.
__device__ __forceinline__ void load_tile(float* __restrict__ dst,
                                          const float* __restrict__ src,
                                          const float* __restrict__ sgn,
                                          int kbase, int tid) {
    #pragma unroll 4
    for (int idx = tid; idx < BC * (KCH / 2); idx += 256) {
        int c  = idx / (KCH / 2);
        int k  = (idx - c * (KCH / 2)) * 2;
        float2 v = *reinterpret_cast<const float2*>(src + c * HW + kbase + k);
        float sc = sgn[c];
        int c4 = c >> 2, cl = c & 3;
        int sw = (k >> 1) & 31;
        int pc = ((c4 ^ sw) << 2) + cl;
        dst[(k    ) * BC + pc] = v.x * sc;
        dst[(k + 1) * BC + pc] = v.y * sc;
    }
}

// ---------------------------------------------------------------------------
// Fused symmetric-block Gram + count-sketch scatter (REDG to global).
// Grid: (10 pairs, 32 batches), 256 threads, 8x8 micro-tile via f32x2 FMA.
// A tiles carry s1, B tiles carry s2 -> forward scatter value = acc;
// mirror value = acc XOR sign masks (sigma_i ^ sigma_j).
extern __shared__ float sm[];
__global__ __launch_bounds__(256, 2) void gram_scatter_kernel(const float* __restrict__ x) {
    const int p = blockIdx.x, b = blockIdx.y;
    const int I = c_I[p], J = c_J[p];
    const bool diag = (I == J);
    float* sA = sm;
    float* sB = sm + KCH * BC;
    const int tid = threadIdx.x;
    const int ti = tid >> 4, tj = tid & 15;
    const float* xb = x + (size_t)b * CIN * HW;

    u64 acc2[8][4];   // acc2[u][v2] = packed {G'[u][2v2], G'[u][2v2+1]}
    #pragma unroll
    for (int u = 0; u < 8; u++)
        #pragma unroll
        for (int v = 0; v < 4; v++) acc2[u][v] = 0ull;

    for (int kc = 0; kc < 2; kc++) {
        if (kc) __syncthreads();
        load_tile(sA, xb + (size_t)I * BC * HW, g_s1 + I * BC, kc * KCH, tid);
        load_tile(sB, xb + (size_t)J * BC * HW, g_s2 + J * BC, kc * KCH, tid);
        __syncthreads();

        const float4*     A4 = reinterpret_cast<const float4*>(sA);
        const ulonglong2* B2 = reinterpret_cast<const ulonglong2*>(sB);
        #pragma unroll 1
        for (int kk = 0; kk < KCH / 2; kk++) {
            const int sw  = kk & 31;
            const int rb  = (2 * kk) * (BC / 4);
            const int ia0 = (ti * 2) ^ sw;
            const int ia1 = ia0 ^ 1;
            const int ib0 = (tj * 2) ^ sw;
            const int ib1 = ib0 ^ 1;

            #pragma unroll
            for (int h = 0; h < 2; h++) {
                const int r = rb + h * (BC / 4);
                float4     a0 = A4[r + ia0];
                float4     a1 = A4[r + ia1];
                ulonglong2 b0 = B2[r + ib0];
                ulonglong2 b1 = B2[r + ib1];
                float ar[8] = {a0.x,a0.y,a0.z,a0.w,a1.x,a1.y,a1.z,a1.w};
                #pragma unroll
                for (int u = 0; u < 8; u++) {
                    u64 ad = pack2(ar[u]);
                    fma2(acc2[u][0], ad, b0.x);
                    fma2(acc2[u][1], ad, b0.y);
                    fma2(acc2[u][2], ad, b1.x);
                    fma2(acc2[u][3], ad, b1.y);
                }
            }
        }
    }

    // ---- scatter ----
    const int ib = I * BC + ti * 8;
    const int jb = J * BC + tj * 8;
    float* Yb = g_Y + b * DPROJ;

    float accm[8][8];
    #pragma unroll
    for (int u = 0; u < 8; u++)
        #pragma unroll
        for (int v2 = 0; v2 < 4; v2++) {
            float2 t = unpack2(acc2[u][v2]);
            accm[u][2 * v2]     = t.x;
            accm[u][2 * v2 + 1] = t.y;
        }

    int h1i[8], h2j[8];
    #pragma unroll
    for (int u = 0; u < 8; u++) h1i[u] = g_h1[ib + u];
    #pragma unroll
    for (int v = 0; v < 8; v++) h2j[v] = g_h2[jb + v];

    // forward: y[(h1[i]+h2[j]) & M] += acc  (signs already folded)
    #pragma unroll
    for (int u = 0; u < 8; u++)
        #pragma unroll
        for (int v = 0; v < 8; v++)
            atomicAdd(Yb + ((h1i[u] + h2j[v]) & (DPROJ - 1)), accm[u][v]);

    if (!diag) {   // mirror (J,I): value = acc * sigma[i]*sigma[j], sigma = s1*s2
        uint32_t su[8], sv[8];
        int h1j[8], h2i[8];
        #pragma unroll
        for (int u = 0; u < 8; u++) {
            h2i[u] = g_h2[ib + u];
            su[u] = (__float_as_uint(g_s1[ib + u]) ^ __float_as_uint(g_s2[ib + u])) & 0x80000000u;
        }
        #pragma unroll
        for (int v = 0; v < 8; v++) {
            h1j[v] = g_h1[jb + v];
            sv[v] = (__float_as_uint(g_s1[jb + v]) ^ __float_as_uint(g_s2[jb + v])) & 0x80000000u;
        }
        #pragma unroll
        for (int u = 0; u < 8; u++)
            #pragma unroll
            for (int v = 0; v < 8; v++) {
                float mv = __uint_as_float(__float_as_uint(accm[u][v]) ^ su[u] ^ sv[v]);
                atomicAdd(Yb + ((h1j[v] + h2i[u]) & (DPROJ - 1)), mv);
            }
    }
}

// ---------------------------------------------------------------------------
// signed sqrt + L2 normalize per image
__global__ void finalize_kernel(float* __restrict__ out) {
    const int b = blockIdx.x, tid = threadIdx.x;
    float v[DPROJ / 256];
    float ss = 0.f;
    #pragma unroll
    for (int m = 0; m < DPROJ / 256; m++) {
        float y = g_Y[b * DPROJ + m * 256 + tid];
        float sv;
        if (y > 0.f)      sv =  sqrtf(y + 1e-8f);
        else if (y < 0.f) sv = -sqrtf(-y + 1e-8f);
        else              sv = 0.f;
        v[m] = sv;
        ss += sv * sv;
    }
    #pragma unroll
    for (int o = 16; o > 0; o >>= 1) ss += __shfl_xor_sync(0xffffffffu, ss, o);
    __shared__ float wsum[8];
    __shared__ float total;
    if ((tid & 31) == 0) wsum[tid >> 5] = ss;
    __syncthreads();
    if (tid == 0) {
        float t = 0.f;
        #pragma unroll
        for (int w = 0; w < 8; w++) t += wsum[w];
        total = t;
    }
    __syncthreads();
    float inv = 1.0f / fmaxf(sqrtf(total), 1e-12f);
    #pragma unroll
    for (int m = 0; m < DPROJ / 256; m++)
        out[b * DPROJ + m * 256 + tid] = v[m] * inv;
}

// ---------------------------------------------------------------------------
extern "C" void kernel_launch(void* const* d_in, const int* in_sizes, int n_in,
                              void* d_out, int out_size) {
    (void)in_sizes; (void)n_in; (void)out_size;
    const float* x  = (const float*)d_in[0];
    const float* S1 = (const float*)d_in[1];
    const float* S2 = (const float*)d_in[2];
    float* out = (float*)d_out;

    const size_t smem_bytes = (size_t)(2 * KCH * BC) * sizeof(float); // 100352 B
    cudaFuncSetAttribute(gram_scatter_kernel,
                         cudaFuncAttributeMaxDynamicSharedMemorySize,
                         (int)smem_bytes);

    prep_kernel<<<2 * CIN + (NB * DPROJ / 4) / 256, 256>>>(S1, S2);

    dim3 grid(NPAIR, NB);
    gram_scatter_kernel<<<grid, 256, smem_bytes>>>(x);

    finalize_kernel<<<NB, 256>>>(out);
}